// round 2
// baseline (speedup 1.0000x reference)
#include <cuda_runtime.h>
#include <math.h>

// Problem dims (fixed by the reference)
#define TT  512
#define BB  64
#define NIN 1024
#define HH  1024
#define GG  4096              // 4*HH
#define TBH (TT*BB*HH)
#define NCTA 128

typedef unsigned long long u64;

// Scratch (allocation-free rule: static __device__ globals)
__device__ float g_Zx[(size_t)TT*BB*GG];   // 512 MB: X@Wx + b
__device__ float g_P[4*BB*GG];             // 4 MB: split-K partials
__device__ u64   g_bar;                    // grid barrier (monotonic)

// ---- packed f32x2 helpers ----
__device__ __forceinline__ u64 pack_dup(float x) {
    u64 r; unsigned xi = __float_as_uint(x);
    asm("mov.b64 %0, {%1, %1};" : "=l"(r) : "r"(xi));
    return r;
}
__device__ __forceinline__ u64 pk2(float x, float y) {
    u64 r;
    asm("mov.b64 %0, {%1, %2};" : "=l"(r)
        : "r"(__float_as_uint(x)), "r"(__float_as_uint(y)));
    return r;
}
__device__ __forceinline__ void ffma2(u64& d, u64 a, u64 b) {
    asm("fma.rn.f32x2 %0, %1, %2, %0;" : "+l"(d) : "l"(a), "l"(b));
}
__device__ __forceinline__ float2 unpk(u64 v) {
    unsigned lo, hi;
    asm("mov.b64 {%0, %1}, %2;" : "=r"(lo), "=r"(hi) : "l"(v));
    return make_float2(__uint_as_float(lo), __uint_as_float(hi));
}

// ============================================================
// Kernel 1: Zx = X @ Wx + b  (M=32768, N=4096, K=1024) — validated round 1
// ============================================================
__global__ __launch_bounds__(256)
void zx_gemm(const float* __restrict__ X, const float* __restrict__ W,
             const float* __restrict__ bias)
{
    __shared__ __align__(16) float As[8][128];
    __shared__ __align__(16) float Bs[8][128];
    const int tid  = threadIdx.x;
    const int brow = blockIdx.y * 128;
    const int bcol = blockIdx.x * 128;
    const int tx = tid & 15, ty = tid >> 4;

    const int a_row = tid >> 1;
    const int a_k   = (tid & 1) * 4;
    const int b_k   = tid >> 5;
    const int b_col = (tid & 31) * 4;

    const float* Ag = X + (size_t)(brow + a_row) * NIN + a_k;
    const float* Bg = W + (size_t)b_k * GG + bcol + b_col;

    float4 af = *(const float4*)Ag;
    float4 bf = *(const float4*)Bg;

    u64 acc[8][4];
    #pragma unroll
    for (int i = 0; i < 8; i++)
        #pragma unroll
        for (int j = 0; j < 4; j++) acc[i][j] = 0ull;

    for (int k0 = 0; k0 < NIN; k0 += 8) {
        As[a_k+0][a_row] = af.x; As[a_k+1][a_row] = af.y;
        As[a_k+2][a_row] = af.z; As[a_k+3][a_row] = af.w;
        *(float4*)&Bs[b_k][b_col] = bf;
        __syncthreads();
        if (k0 + 8 < NIN) {
            af = *(const float4*)(Ag + k0 + 8);
            bf = *(const float4*)(Bg + (size_t)(k0 + 8) * GG);
        }
        #pragma unroll
        for (int k = 0; k < 8; k++) {
            u64 bb[4];
            #pragma unroll
            for (int j = 0; j < 4; j++)
                bb[j] = *(const u64*)&Bs[k][tx*2 + j*32];
            #pragma unroll
            for (int i = 0; i < 8; i++) {
                u64 aa = pack_dup(As[k][ty*8 + i]);
                #pragma unroll
                for (int j = 0; j < 4; j++) ffma2(acc[i][j], aa, bb[j]);
            }
        }
        __syncthreads();
    }
    #pragma unroll
    for (int i = 0; i < 8; i++) {
        const size_t row = (size_t)(brow + ty*8 + i);
        #pragma unroll
        for (int j = 0; j < 4; j++) {
            const int col = bcol + tx*2 + j*32;
            float2 v = unpk(acc[i][j]);
            v.x += bias[col];
            v.y += bias[col + 1];
            *(float2*)&g_Zx[row * GG + col] = v;
        }
    }
}

// ============================================================
// Grid barrier: monotonic counter, no reset needed across replays
// (arrivals per launch = 1024 barriers * 128 CTAs -> stays 128-aligned).
// ============================================================
__device__ __forceinline__ void grid_barrier()
{
    __syncthreads();
    if (threadIdx.x == 0) {
        __threadfence();                       // release prior STGs
        u64 my = atomicAdd(&g_bar, 1ULL);
        u64 target = (my / NCTA + 1ULL) * NCTA;
        volatile u64* p = &g_bar;
        while (*p < target) { }
        __threadfence();                       // acquire
    }
    __syncthreads();
}

// ============================================================
// Kernel 2: persistent LSTM recurrence.
// Grid 128 CTAs x 128 threads. CTA (ks, cg): K-split ks*256..+256,
// cols cg*128..+128. Wh slice (128 KB) persists in smem all 512 steps.
// Per-thread 8x8 tile, ffma2 paired over K, XOR-swizzled smem.
// ============================================================
__global__ __launch_bounds__(128, 1)
void lstm_persist(const float* __restrict__ W,
                  const float* __restrict__ y0,
                  const float* __restrict__ c0,
                  const float* __restrict__ mask,
                  float* __restrict__ Y, float* __restrict__ C,
                  float* __restrict__ cT)
{
    extern __shared__ __align__(16) u64 smem[];
    u64* Bs = smem;              // [128 cols][128 u64 units]  = 128 KB
    u64* As = smem + 128*128;    // [64 rows][128 u64 units]   =  64 KB

    const int tid = threadIdx.x;
    const int bx  = blockIdx.x;
    const int ks  = bx >> 5;          // 0..3   K-split
    const int cgb = (bx & 31) * 128;  // column base in [0,4096)
    const int kb  = ks * 256;         // K base within Wh

    // ---- one-time: Wh slice -> Bs, transposed [col][k], swizzled ----
    {
        const int c4 = (tid & 31) * 4;   // 4 consecutive local cols
        const int kr = tid >> 5;         // k residue 0..3
        for (int k = kr; k < 256; k += 4) {
            const float4 v = *(const float4*)&W[(size_t)(NIN + kb + k) * GG + cgb + c4];
            const int u = k >> 1, half = k & 1;
            float vv[4] = {v.x, v.y, v.z, v.w};
            #pragma unroll
            for (int j = 0; j < 4; j++) {
                const int c  = c4 + j;
                const int sw = ((c >> 3) ^ c) & 7;
                ((float*)&Bs[c*128 + (u ^ sw)])[half] = vv[j];
            }
        }
    }
    __syncthreads();

    // thread tile coords: rows rg*8..+7, cols cgi*8..+7 (local)
    const int rg  = tid & 7;
    const int cgi = tid >> 3;            // 0..15
    // A-load assignment
    const int a_b    = tid >> 1;         // row 0..63
    const int a_half = tid & 1;          // K half (128 floats)
    const int a_sw   = ((a_b >> 3) ^ a_b) & 7;

    for (int t = 0; t < TT; t++) {
        const float* yp = (t == 0) ? y0 : (Y + (size_t)(t-1)*BB*HH);

        // ---- load A slice [64 x 256] into As (swizzled) ----
        {
            const float4* src = (const float4*)(yp + (size_t)a_b*HH + kb + a_half*128);
            const int ub = a_half * 64;
            #pragma unroll
            for (int q = 0; q < 32; q++) {
                float4 v = src[q];
                As[a_b*128 + ((ub + 2*q    ) ^ a_sw)] = pk2(v.x, v.y);
                As[a_b*128 + ((ub + 2*q + 1) ^ a_sw)] = pk2(v.z, v.w);
            }
        }
        __syncthreads();

        // ---- GEMM: acc2[r][c] += y2 * w2 over 128 k-pairs ----
        u64 acc[8][8];
        #pragma unroll
        for (int i = 0; i < 8; i++)
            #pragma unroll
            for (int c = 0; c < 8; c++) acc[i][c] = 0ull;

        #pragma unroll 2
        for (int p = 0; p < 128; p++) {
            u64 a2[8], b2[8];
            #pragma unroll
            for (int i = 0; i < 8; i++)
                a2[i] = As[(rg*8 + i)*128 + (p ^ (rg ^ i))];
            #pragma unroll
            for (int c = 0; c < 8; c++)
                b2[c] = Bs[(cgi*8 + c)*128 + (p ^ ((cgi ^ c) & 7))];
            #pragma unroll
            for (int i = 0; i < 8; i++)
                #pragma unroll
                for (int c = 0; c < 8; c++)
                    ffma2(acc[i][c], a2[i], b2[c]);
        }
        __syncthreads();   // As reuse safety for next step's fill

        // ---- write K-split partials (lo+hi fold) ----
        #pragma unroll
        for (int i = 0; i < 8; i++) {
            const int r = rg*8 + i;
            float o[8];
            #pragma unroll
            for (int c = 0; c < 8; c++) {
                float2 f = unpk(acc[i][c]);
                o[c] = f.x + f.y;
            }
            float* dst = &g_P[(size_t)(ks*BB + r)*GG + cgb + cgi*8];
            *(float4*)(dst)     = make_float4(o[0], o[1], o[2], o[3]);
            *(float4*)(dst + 4) = make_float4(o[4], o[5], o[6], o[7]);
        }

        grid_barrier();   // all partials visible

        // ---- gates: 512 cells per CTA, coalesced in h ----
        #pragma unroll
        for (int q = 0; q < 4; q++) {
            const int cell = bx*512 + q*128 + tid;   // = b*1024 + h
            const int b = cell >> 10, h = cell & 1023;
            const float* zx = g_Zx + ((size_t)t*BB + b)*GG + h;
            float z[4];
            #pragma unroll
            for (int g = 0; g < 4; g++) {
                float s = zx[g*HH];
                #pragma unroll
                for (int kk = 0; kk < 4; kk++)
                    s += g_P[(size_t)(kk*BB + b)*GG + g*HH + h];
                z[g] = s;
            }
            const float ci = tanhf(z[0]);
            const float ig = 1.f / (1.f + expf(-z[1]));
            const float fg = 1.f / (1.f + expf(-z[2]));
            const float og = 1.f / (1.f + expf(-z[3]));
            const float cp = (t == 0) ? c0[cell]
                                      : C[(size_t)(t-1)*BB*HH + cell];
            float c = ci*ig + cp*fg;
            float y = tanhf(c)*og;
            const float m = mask[t*BB + b];
            c = m*c + (1.f - m)*cp;
            y = m*y;
            C[(size_t)t*BB*HH + cell] = c;
            Y[(size_t)t*BB*HH + cell] = y;
            if (t == TT-1) cT[cell] = c;
        }

        grid_barrier();   // Y[t] visible before next step's A loads
    }
}

// ============================================================
extern "C" void kernel_launch(void* const* d_in, const int* in_sizes, int n_in,
                              void* d_out, int out_size)
{
    const float* X    = (const float*)d_in[0];   // [512,64,1024]
    const float* W    = (const float*)d_in[1];   // [2048,4096]
    const float* bias = (const float*)d_in[2];   // [4096]
    const float* y0   = (const float*)d_in[3];   // [64,1024]
    const float* c0   = (const float*)d_in[4];   // [64,1024]
    const float* mask = (const float*)d_in[5];   // [512,64]

    float* out = (float*)d_out;
    float* Y  = out;                       // [512,64,1024]
    float* C  = out + (size_t)TBH;         // [512,64,1024]
    float* cT = out + 2 * (size_t)TBH;     // [64,1024]

    cudaFuncSetAttribute(lstm_persist,
                         cudaFuncAttributeMaxDynamicSharedMemorySize, 196608);

    // Node 1: input projection for all timesteps.
    zx_gemm<<<dim3(GG/128, (TT*BB)/128), 256>>>(X, W, bias);
    // Node 2: full recurrence in one persistent kernel.
    lstm_persist<<<NCTA, 128, 196608>>>(W, y0, c0, mask, Y, C, cT);
}

// round 4
// speedup vs baseline: 1.9367x; 1.9367x over previous
#include <cuda_runtime.h>
#include <math.h>

// Problem dims (fixed by the reference)
#define TT  512
#define BB  64
#define NIN 1024
#define HH  1024
#define GG  4096              // 4*HH
#define TBH (TT*BB*HH)
#define NCTA 128
#define KSPLIT 8
#define KSLICE 128            // NIN / KSPLIT
#define NCOLS 256             // columns per CTA

typedef unsigned long long u64;

// Scratch (allocation-free rule: static __device__ globals)
__device__ float g_Zx[(size_t)TT*BB*GG];      // 512 MB: X@Wx + b
__device__ float g_P[KSPLIT*BB*GG];           // 8 MB: split-K partials
__device__ u64   g_bar;                       // grid barrier (monotonic)

// ---- packed f32x2 helpers ----
__device__ __forceinline__ u64 pack_dup(float x) {
    u64 r; unsigned xi = __float_as_uint(x);
    asm("mov.b64 %0, {%1, %1};" : "=l"(r) : "r"(xi));
    return r;
}
__device__ __forceinline__ void ffma2(u64& d, u64 a, u64 b) {
    asm("fma.rn.f32x2 %0, %1, %2, %0;" : "+l"(d) : "l"(a), "l"(b));
}
__device__ __forceinline__ float2 unpk(u64 v) {
    unsigned lo, hi;
    asm("mov.b64 {%0, %1}, %2;" : "=r"(lo), "=r"(hi) : "l"(v));
    return make_float2(__uint_as_float(lo), __uint_as_float(hi));
}

// ============================================================
// Kernel 1: Zx = X @ Wx + b  (M=32768, N=4096, K=1024) — validated
// ============================================================
__global__ __launch_bounds__(256)
void zx_gemm(const float* __restrict__ X, const float* __restrict__ W,
             const float* __restrict__ bias)
{
    __shared__ __align__(16) float As[8][128];
    __shared__ __align__(16) float Bs[8][128];
    const int tid  = threadIdx.x;
    const int brow = blockIdx.y * 128;
    const int bcol = blockIdx.x * 128;
    const int tx = tid & 15, ty = tid >> 4;

    const int a_row = tid >> 1;
    const int a_k   = (tid & 1) * 4;
    const int b_k   = tid >> 5;
    const int b_col = (tid & 31) * 4;

    const float* Ag = X + (size_t)(brow + a_row) * NIN + a_k;
    const float* Bg = W + (size_t)b_k * GG + bcol + b_col;

    float4 af = *(const float4*)Ag;
    float4 bf = *(const float4*)Bg;

    u64 acc[8][4];
    #pragma unroll
    for (int i = 0; i < 8; i++)
        #pragma unroll
        for (int j = 0; j < 4; j++) acc[i][j] = 0ull;

    for (int k0 = 0; k0 < NIN; k0 += 8) {
        As[a_k+0][a_row] = af.x; As[a_k+1][a_row] = af.y;
        As[a_k+2][a_row] = af.z; As[a_k+3][a_row] = af.w;
        *(float4*)&Bs[b_k][b_col] = bf;
        __syncthreads();
        if (k0 + 8 < NIN) {
            af = *(const float4*)(Ag + k0 + 8);
            bf = *(const float4*)(Bg + (size_t)(k0 + 8) * GG);
        }
        #pragma unroll
        for (int k = 0; k < 8; k++) {
            u64 bb[4];
            #pragma unroll
            for (int j = 0; j < 4; j++)
                bb[j] = *(const u64*)&Bs[k][tx*2 + j*32];
            #pragma unroll
            for (int i = 0; i < 8; i++) {
                u64 aa = pack_dup(As[k][ty*8 + i]);
                #pragma unroll
                for (int j = 0; j < 4; j++) ffma2(acc[i][j], aa, bb[j]);
            }
        }
        __syncthreads();
    }
    #pragma unroll
    for (int i = 0; i < 8; i++) {
        const size_t row = (size_t)(brow + ty*8 + i);
        #pragma unroll
        for (int j = 0; j < 4; j++) {
            const int col = bcol + tx*2 + j*32;
            float2 v = unpk(acc[i][j]);
            v.x += bias[col];
            v.y += bias[col + 1];
            *(float2*)&g_Zx[row * GG + col] = v;
        }
    }
}

// ============================================================
// Grid barrier: monotonic counter, no reset across graph replays
// (arrivals/launch = 1024 barriers * 128 CTAs -> stays 128-aligned).
// ============================================================
__device__ __forceinline__ void grid_barrier()
{
    __syncthreads();
    if (threadIdx.x == 0) {
        __threadfence();
        u64 my = atomicAdd(&g_bar, 1ULL);
        u64 target = (my / NCTA + 1ULL) * NCTA;
        volatile u64* p = &g_bar;
        while (*p < target) { }
        __threadfence();
    }
    __syncthreads();
}

// ============================================================
// Kernel 2: persistent LSTM recurrence (restructured).
// 128 CTAs x 256 threads. CTA (ks, cg): K-slice ks*128..+128,
// cols cg*256..+256. Per-thread 8x8 tile, COL-paired f32x2 accs
// (32 u64 = 64 regs). Wh slice [128k x 256c] f32 persists in smem;
// y rows stored DUPLICATED as (a,a) u64 -> all operand loads are
// broadcast/contiguous LDS.128, zero conflicts, zero dup-movs.
// ============================================================
__global__ __launch_bounds__(256, 1)
void lstm_persist(const float* __restrict__ W,
                  const float* __restrict__ y0,
                  const float* __restrict__ c0,
                  const float* __restrict__ mask,
                  float* __restrict__ Y, float* __restrict__ C,
                  float* __restrict__ cT)
{
    extern __shared__ __align__(16) char smem[];
    float* Bs = (float*)smem;                       // [128][256] = 128 KB
    u64*   As = (u64*)(smem + KSLICE*NCOLS*4);      // [128][64] u64 = 64 KB

    const int tid = threadIdx.x;
    const int bx  = blockIdx.x;
    const int ks  = bx >> 4;            // 0..7   K-split
    const int cgb = (bx & 15) * NCOLS;  // column base in [0,4096)
    const int kb  = ks * KSLICE;        // K base within Wh

    // thread tile: rows ry*8..+7, cols cx*8..+7 (local)
    const int cx = tid & 31;            // 0..31 col-group
    const int ry = tid >> 5;            // 0..7  row-group

    // ---- one-time: Wh slice -> Bs [k][col], row-major, coalesced ----
    {
        const int c4 = (tid & 63) * 4;      // col 0..252
        const int kr = tid >> 6;            // 0..3
        for (int k = kr; k < KSLICE; k += 4) {
            *(float4*)&Bs[k*NCOLS + c4] =
                *(const float4*)&W[(size_t)(NIN + kb + k) * GG + cgb + c4];
        }
    }

    // A-fill assignment: row = tid&63, k-quarter = tid>>6
    const int a_row = tid & 63;
    const int a_kq  = tid >> 6;          // 0..3 -> k = a_kq*32 .. +32
    __syncthreads();

    for (int t = 0; t < TT; t++) {
        const float* yp = (t == 0) ? y0 : (Y + (size_t)(t-1)*BB*HH);

        // ---- fill As[k][row] = (y,y) dup'd, transposed ----
        {
            const float* src = yp + (size_t)a_row*HH + kb + a_kq*32;
            #pragma unroll
            for (int j = 0; j < 8; j++) {
                float4 v = *(const float4*)(src + j*4);
                const int k0 = a_kq*32 + j*4;
                As[(k0+0)*64 + a_row] = pack_dup(v.x);
                As[(k0+1)*64 + a_row] = pack_dup(v.y);
                As[(k0+2)*64 + a_row] = pack_dup(v.z);
                As[(k0+3)*64 + a_row] = pack_dup(v.w);
            }
        }
        __syncthreads();

        // ---- GEMM: 8 rows x 4 col-pairs, K=128 ----
        u64 acc[8][4];
        #pragma unroll
        for (int i = 0; i < 8; i++)
            #pragma unroll
            for (int j = 0; j < 4; j++) acc[i][j] = 0ull;

        #pragma unroll 4
        for (int p = 0; p < KSLICE; p++) {
            ulonglong2 a01 = *(const ulonglong2*)&As[p*64 + ry*8 + 0];
            ulonglong2 a23 = *(const ulonglong2*)&As[p*64 + ry*8 + 2];
            ulonglong2 a45 = *(const ulonglong2*)&As[p*64 + ry*8 + 4];
            ulonglong2 a67 = *(const ulonglong2*)&As[p*64 + ry*8 + 6];
            ulonglong2 b01 = *(const ulonglong2*)&Bs[p*NCOLS + cx*8];
            ulonglong2 b23 = *(const ulonglong2*)&Bs[p*NCOLS + cx*8 + 4];
            u64 a[8] = {a01.x, a01.y, a23.x, a23.y, a45.x, a45.y, a67.x, a67.y};
            u64 b[4] = {b01.x, b01.y, b23.x, b23.y};
            #pragma unroll
            for (int i = 0; i < 8; i++)
                #pragma unroll
                for (int j = 0; j < 4; j++)
                    ffma2(acc[i][j], a[i], b[j]);
        }

        // ---- write K-split partials (col-paired accs ARE outputs) ----
        #pragma unroll
        for (int i = 0; i < 8; i++) {
            const int r = ry*8 + i;
            float* dst = &g_P[(size_t)(ks*BB + r)*GG + cgb + cx*8];
            float2 v0 = unpk(acc[i][0]), v1 = unpk(acc[i][1]);
            float2 v2 = unpk(acc[i][2]), v3 = unpk(acc[i][3]);
            *(float4*)(dst)     = make_float4(v0.x, v0.y, v1.x, v1.y);
            *(float4*)(dst + 4) = make_float4(v2.x, v2.y, v3.x, v3.y);
        }

        grid_barrier();   // all partials visible

        // ---- gates: 2 cells per thread, coalesced in h ----
        #pragma unroll
        for (int q = 0; q < 2; q++) {
            const int cell = bx*512 + q*256 + tid;   // = b*1024 + h
            const int b = cell >> 10, h = cell & 1023;
            const float* zx = g_Zx + ((size_t)t*BB + b)*GG + h;
            float z[4];
            #pragma unroll
            for (int g = 0; g < 4; g++) {
                float s = zx[g*HH];
                #pragma unroll
                for (int kk = 0; kk < KSPLIT; kk++)
                    s += g_P[(size_t)(kk*BB + b)*GG + g*HH + h];
                z[g] = s;
            }
            const float ci = tanhf(z[0]);
            const float ig = 1.f / (1.f + expf(-z[1]));
            const float fg = 1.f / (1.f + expf(-z[2]));
            const float og = 1.f / (1.f + expf(-z[3]));
            const float cp = (t == 0) ? c0[cell]
                                      : C[(size_t)(t-1)*BB*HH + cell];
            float c = ci*ig + cp*fg;
            float y = tanhf(c)*og;
            const float m = mask[t*BB + b];
            c = m*c + (1.f - m)*cp;
            y = m*y;
            C[(size_t)t*BB*HH + cell] = c;
            Y[(size_t)t*BB*HH + cell] = y;
            if (t == TT-1) cT[cell] = c;
        }

        grid_barrier();   // Y[t] visible before next step's A fill
    }
}

// ============================================================
extern "C" void kernel_launch(void* const* d_in, const int* in_sizes, int n_in,
                              void* d_out, int out_size)
{
    const float* X    = (const float*)d_in[0];   // [512,64,1024]
    const float* W    = (const float*)d_in[1];   // [2048,4096]
    const float* bias = (const float*)d_in[2];   // [4096]
    const float* y0   = (const float*)d_in[3];   // [64,1024]
    const float* c0   = (const float*)d_in[4];   // [64,1024]
    const float* mask = (const float*)d_in[5];   // [512,64]

    float* out = (float*)d_out;
    float* Y  = out;                       // [512,64,1024]
    float* C  = out + (size_t)TBH;         // [512,64,1024]
    float* cT = out + 2 * (size_t)TBH;     // [64,1024]

    cudaFuncSetAttribute(lstm_persist,
                         cudaFuncAttributeMaxDynamicSharedMemorySize, 196608);

    // Node 1: input projection for all timesteps.
    zx_gemm<<<dim3(GG/128, (TT*BB)/128), 256>>>(X, W, bias);
    // Node 2: full recurrence in one persistent kernel.
    lstm_persist<<<NCTA, 256, 196608>>>(W, y0, c0, mask, Y, C, cT);
}

// round 9
// speedup vs baseline: 2.0259x; 1.0461x over previous
#include <cuda_runtime.h>
#include <math.h>

// Problem dims (fixed by the reference)
#define TT  512
#define BB  64
#define NIN 1024
#define HH  1024
#define GG  4096              // 4*HH
#define TBH (TT*BB*HH)
#define NCTA 128
#define NTHR 512
#define KSPLIT 8
#define KSLICE 128            // NIN / KSPLIT
#define NCOLS 256             // columns per CTA

typedef unsigned long long u64;

// Scratch (allocation-free rule: static __device__ globals)
__device__ float g_Zx[(size_t)TT*BB*GG];      // 512 MB: X@Wx + b
__device__ float g_P[KSPLIT*BB*GG];           // 8 MB: split-K partials
__device__ u64   g_bar;                       // grid barrier (monotonic)

// ---- packed f32x2 helpers ----
__device__ __forceinline__ u64 pack_dup(float x) {
    u64 r; unsigned xi = __float_as_uint(x);
    asm("mov.b64 %0, {%1, %1};" : "=l"(r) : "r"(xi));
    return r;
}
__device__ __forceinline__ void ffma2(u64& d, u64 a, u64 b) {
    asm("fma.rn.f32x2 %0, %1, %2, %0;" : "+l"(d) : "l"(a), "l"(b));
}
__device__ __forceinline__ float2 unpk(u64 v) {
    unsigned lo, hi;
    asm("mov.b64 {%0, %1}, %2;" : "=r"(lo), "=r"(hi) : "l"(v));
    return make_float2(__uint_as_float(lo), __uint_as_float(hi));
}

// ============================================================
// Kernel 1: Zx = X @ Wx + b  (M=32768, N=4096, K=1024) — validated
// ============================================================
__global__ __launch_bounds__(256)
void zx_gemm(const float* __restrict__ X, const float* __restrict__ W,
             const float* __restrict__ bias)
{
    __shared__ __align__(16) float As[8][128];
    __shared__ __align__(16) float Bs[8][128];
    const int tid  = threadIdx.x;
    const int brow = blockIdx.y * 128;
    const int bcol = blockIdx.x * 128;
    const int tx = tid & 15, ty = tid >> 4;

    const int a_row = tid >> 1;
    const int a_k   = (tid & 1) * 4;
    const int b_k   = tid >> 5;
    const int b_col = (tid & 31) * 4;

    const float* Ag = X + (size_t)(brow + a_row) * NIN + a_k;
    const float* Bg = W + (size_t)b_k * GG + bcol + b_col;

    float4 af = *(const float4*)Ag;
    float4 bf = *(const float4*)Bg;

    u64 acc[8][4];
    #pragma unroll
    for (int i = 0; i < 8; i++)
        #pragma unroll
        for (int j = 0; j < 4; j++) acc[i][j] = 0ull;

    for (int k0 = 0; k0 < NIN; k0 += 8) {
        As[a_k+0][a_row] = af.x; As[a_k+1][a_row] = af.y;
        As[a_k+2][a_row] = af.z; As[a_k+3][a_row] = af.w;
        *(float4*)&Bs[b_k][b_col] = bf;
        __syncthreads();
        if (k0 + 8 < NIN) {
            af = *(const float4*)(Ag + k0 + 8);
            bf = *(const float4*)(Bg + (size_t)(k0 + 8) * GG);
        }
        #pragma unroll
        for (int k = 0; k < 8; k++) {
            u64 bb[4];
            #pragma unroll
            for (int j = 0; j < 4; j++)
                bb[j] = *(const u64*)&Bs[k][tx*2 + j*32];
            #pragma unroll
            for (int i = 0; i < 8; i++) {
                u64 aa = pack_dup(As[k][ty*8 + i]);
                #pragma unroll
                for (int j = 0; j < 4; j++) ffma2(acc[i][j], aa, bb[j]);
            }
        }
        __syncthreads();
    }
    #pragma unroll
    for (int i = 0; i < 8; i++) {
        const size_t row = (size_t)(brow + ty*8 + i);
        #pragma unroll
        for (int j = 0; j < 4; j++) {
            const int col = bcol + tx*2 + j*32;
            float2 v = unpk(acc[i][j]);
            v.x += bias[col];
            v.y += bias[col + 1];
            *(float2*)&g_Zx[row * GG + col] = v;
        }
    }
}

// ============================================================
// Grid barrier: monotonic counter, no reset across graph replays
// (arrivals/launch = 1024 barriers * 128 CTAs -> stays 128-aligned).
// ============================================================
__device__ __forceinline__ void grid_barrier()
{
    __syncthreads();
    if (threadIdx.x == 0) {
        __threadfence();
        u64 my = atomicAdd(&g_bar, 1ULL);
        u64 target = (my / NCTA + 1ULL) * NCTA;
        volatile u64* p = &g_bar;
        while (*p < target) { }
        __threadfence();
    }
    __syncthreads();
}

// ============================================================
// Kernel 2: persistent LSTM recurrence.
// 128 CTAs x 512 threads (16 warps -> 4/SMSP for latency hiding).
// CTA (ks, cg): K-slice ks*128..+128, cols cg*256..+256.
// Per-thread 8 rows x 4 cols, col-paired f32x2 accs (16 u64 = 32 regs).
// Wh slice [128k x 256c] f32 + dup'd y [128k x 64r] u64 in smem.
// ============================================================
__global__ __launch_bounds__(NTHR, 1)
void lstm_persist(const float* __restrict__ W,
                  const float* __restrict__ y0,
                  const float* __restrict__ c0,
                  const float* __restrict__ mask,
                  float* __restrict__ Y, float* __restrict__ C,
                  float* __restrict__ cT)
{
    extern __shared__ __align__(16) char smem[];
    float* Bs = (float*)smem;                       // [128][256] = 128 KB
    u64*   As = (u64*)(smem + KSLICE*NCOLS*4);      // [128][64] u64 = 64 KB

    const int tid = threadIdx.x;
    const int bx  = blockIdx.x;
    const int ks  = bx >> 4;            // 0..7   K-split
    const int cgb = (bx & 15) * NCOLS;  // column base in [0,4096)
    const int kb  = ks * KSLICE;        // K base within Wh

    // thread tile: rows ry*8..+7, cols cx*4..+3 (local)
    const int cx = tid & 63;            // 0..63 col-group (4 cols)
    const int ry = tid >> 6;            // 0..7  row-group (8 rows)

    // ---- one-time: Wh slice -> Bs [k][col], row-major, coalesced ----
    {
        const int c4 = (tid & 63) * 4;      // col 0..252
        const int kr = tid >> 6;            // 0..7
        for (int k = kr; k < KSLICE; k += 8) {
            *(float4*)&Bs[k*NCOLS + c4] =
                *(const float4*)&W[(size_t)(NIN + kb + k) * GG + cgb + c4];
        }
    }

    // A-fill assignment: row = tid&63, k-eighth = tid>>6 (16 k each)
    const int a_row = tid & 63;
    const int a_kq  = tid >> 6;          // 0..7 -> k = a_kq*16 .. +16
    __syncthreads();

    for (int t = 0; t < TT; t++) {
        const float* yp = (t == 0) ? y0 : (Y + (size_t)(t-1)*BB*HH);

        // ---- fill As[k][row] = (y,y) dup'd, transposed ----
        {
            const float* src = yp + (size_t)a_row*HH + kb + a_kq*16;
            #pragma unroll
            for (int j = 0; j < 4; j++) {
                float4 v = *(const float4*)(src + j*4);
                const int k0 = a_kq*16 + j*4;
                As[(k0+0)*64 + a_row] = pack_dup(v.x);
                As[(k0+1)*64 + a_row] = pack_dup(v.y);
                As[(k0+2)*64 + a_row] = pack_dup(v.z);
                As[(k0+3)*64 + a_row] = pack_dup(v.w);
            }
        }
        __syncthreads();

        // ---- GEMM: 8 rows x 2 col-pairs, K=128 ----
        u64 acc[8][2];
        #pragma unroll
        for (int i = 0; i < 8; i++) { acc[i][0] = 0ull; acc[i][1] = 0ull; }

        #pragma unroll 4
        for (int p = 0; p < KSLICE; p++) {
            ulonglong2 a01 = *(const ulonglong2*)&As[p*64 + ry*8 + 0];
            ulonglong2 a23 = *(const ulonglong2*)&As[p*64 + ry*8 + 2];
            ulonglong2 a45 = *(const ulonglong2*)&As[p*64 + ry*8 + 4];
            ulonglong2 a67 = *(const ulonglong2*)&As[p*64 + ry*8 + 6];
            ulonglong2 b01 = *(const ulonglong2*)&Bs[p*NCOLS + cx*4];
            u64 a[8] = {a01.x, a01.y, a23.x, a23.y, a45.x, a45.y, a67.x, a67.y};
            #pragma unroll
            for (int i = 0; i < 8; i++) {
                ffma2(acc[i][0], a[i], b01.x);
                ffma2(acc[i][1], a[i], b01.y);
            }
        }

        // ---- write K-split partials (col-paired accs ARE outputs) ----
        #pragma unroll
        for (int i = 0; i < 8; i++) {
            const int r = ry*8 + i;
            float2 v0 = unpk(acc[i][0]), v1 = unpk(acc[i][1]);
            *(float4*)&g_P[(size_t)(ks*BB + r)*GG + cgb + cx*4] =
                make_float4(v0.x, v0.y, v1.x, v1.y);
        }

        grid_barrier();   // all partials visible

        // ---- gates: 1 cell per thread, coalesced in h ----
        {
            const int cell = bx*512 + tid;   // = b*1024 + h
            const int b = cell >> 10, h = cell & 1023;
            const float* zx = g_Zx + ((size_t)t*BB + b)*GG + h;
            float z[4];
            #pragma unroll
            for (int g = 0; g < 4; g++) {
                float s = zx[g*HH];
                #pragma unroll
                for (int kk = 0; kk < KSPLIT; kk++)
                    s += g_P[(size_t)(kk*BB + b)*GG + g*HH + h];
                z[g] = s;
            }
            const float ci = tanhf(z[0]);
            const float ig = 1.f / (1.f + expf(-z[1]));
            const float fg = 1.f / (1.f + expf(-z[2]));
            const float og = 1.f / (1.f + expf(-z[3]));
            const float cp = (t == 0) ? c0[cell]
                                      : C[(size_t)(t-1)*BB*HH + cell];
            float c = ci*ig + cp*fg;
            float y = tanhf(c)*og;
            const float m = mask[t*BB + b];
            c = m*c + (1.f - m)*cp;
            y = m*y;
            C[(size_t)t*BB*HH + cell] = c;
            Y[(size_t)t*BB*HH + cell] = y;
            if (t == TT-1) cT[cell] = c;
        }

        grid_barrier();   // Y[t] visible before next step's A fill
    }
}

// ============================================================
extern "C" void kernel_launch(void* const* d_in, const int* in_sizes, int n_in,
                              void* d_out, int out_size)
{
    const float* X    = (const float*)d_in[0];   // [512,64,1024]
    const float* W    = (const float*)d_in[1];   // [2048,4096]
    const float* bias = (const float*)d_in[2];   // [4096]
    const float* y0   = (const float*)d_in[3];   // [64,1024]
    const float* c0   = (const float*)d_in[4];   // [64,1024]
    const float* mask = (const float*)d_in[5];   // [512,64]

    float* out = (float*)d_out;
    float* Y  = out;                       // [512,64,1024]
    float* C  = out + (size_t)TBH;         // [512,64,1024]
    float* cT = out + 2 * (size_t)TBH;     // [64,1024]

    cudaFuncSetAttribute(lstm_persist,
                         cudaFuncAttributeMaxDynamicSharedMemorySize, 196608);

    // Node 1: input projection for all timesteps.
    zx_gemm<<<dim3(GG/128, (TT*BB)/128), 256>>>(X, W, bias);
    // Node 2: full recurrence in one persistent kernel.
    lstm_persist<<<NCTA, NTHR, 196608>>>(W, y0, c0, mask, Y, C, cT);
}